// round 10
// baseline (speedup 1.0000x reference)
#include <cuda_runtime.h>

#define BB 256
#define TT 4096
#define DD 3
#define UU 8
#define SIGD 21
#define CHUNK 16   // TT / 256 threads (kernel A)
#define PF 4       // lstm prefetch depth (steps) per batch

// Scratch: per (b,t,u): {0.5*z_i, z_c, 0.5*z_o, f}  (biases folded)
// Padded so the branchless prefetch ring can read past the end.
__device__ float4 g_G[(size_t)BB * TT * UU + 16 * UU];

__device__ __forceinline__ float ex2f(float x) {
    float y; asm("ex2.approx.f32 %0, %1;" : "=f"(y) : "f"(x)); return y;
}
__device__ __forceinline__ float rcpf(float x) {
    float y; asm("rcp.approx.f32 %0, %1;" : "=f"(y) : "f"(x)); return y;
}
__device__ __forceinline__ float tanha(float x) {        // MUFU.TANH, 1 op
    float y; asm("tanh.approx.f32 %0, %1;" : "=f"(y) : "f"(x)); return y;
}
__device__ __forceinline__ float fsig(float x) {         // accurate sigmoid (kernel A)
    return rcpf(1.0f + ex2f(-1.4426950408889634f * x));
}

// ---------------------------------------------------------------------------
// Kernel A: signature scan + forget gate + input projection (parallel B x T)
// ---------------------------------------------------------------------------
__global__ __launch_bounds__(256) void sig_kernel(
    const float* __restrict__ inp,   // (B,T,3)
    const float* __restrict__ Wi,    // (3,24)
    const float* __restrict__ Wf,    // (21,8)
    const float* __restrict__ bias)  // (32) = [b_i, b_f, b_c, b_o]
{
    __shared__ float sh[2][256][20];
    __shared__ float swf[SIGD * UU];   // 168
    __shared__ float swi[DD * 3 * UU]; // 72
    __shared__ float sb[4 * UU];       // 32

    const int b = blockIdx.x;
    const int j = threadIdx.x;
    if (j < SIGD * UU)   swf[j] = Wf[j];
    if (j < DD * 3 * UU) swi[j] = Wi[j];
    if (j < 4 * UU)      sb[j]  = bias[j];

    const float dt = 1.0f / (float)(TT - 1);
    const int t0 = j * CHUNK;
    const float* ip = inp + ((size_t)b * TT + t0) * DD;

    // ---- pass 1: local chunk signature (diffs t0+1 .. t0+16) ----
    float L1[4] = {0.f, 0.f, 0.f, 0.f};
    float L2[16] = {0.f};
    {
        float p0 = ip[0], p1 = ip[1], p2 = ip[2];
        #pragma unroll
        for (int s = 1; s <= CHUNK; s++) {
            int tg = t0 + s;
            if (tg <= TT - 1) {
                float c0 = ip[s * DD + 0], c1 = ip[s * DD + 1], c2 = ip[s * DD + 2];
                float dx[4] = {dt, c0 - p0, c1 - p1, c2 - p2};
                #pragma unroll
                for (int p = 0; p < 4; p++) {
                    float a = L1[p] + 0.5f * dx[p];
                    #pragma unroll
                    for (int q = 0; q < 4; q++)
                        L2[p * 4 + q] += a * dx[q];
                }
                #pragma unroll
                for (int p = 0; p < 4; p++) L1[p] += dx[p];
                p0 = c0; p1 = c1; p2 = c2;
            }
        }
    }

    // ---- inclusive Hillis-Steele scan of Chen states over 256 chunks ----
    #pragma unroll
    for (int p = 0; p < 4; p++)  sh[0][j][p] = L1[p];
    #pragma unroll
    for (int p = 0; p < 16; p++) sh[0][j][4 + p] = L2[p];
    __syncthreads();

    int cur = 0;
    for (int ofs = 1; ofs < 256; ofs <<= 1) {
        float v[20];
        #pragma unroll
        for (int p = 0; p < 20; p++) v[p] = sh[cur][j][p];
        if (j >= ofs) {
            const float* a = sh[cur][j - ofs];  // earlier aggregate
            float o[20];
            #pragma unroll
            for (int p = 0; p < 4; p++) o[p] = a[p] + v[p];
            #pragma unroll
            for (int p = 0; p < 4; p++)
                #pragma unroll
                for (int q = 0; q < 4; q++)
                    o[4 + p * 4 + q] = a[4 + p * 4 + q] + v[4 + p * 4 + q] + a[p] * v[q];
            #pragma unroll
            for (int p = 0; p < 20; p++) v[p] = o[p];
        }
        #pragma unroll
        for (int p = 0; p < 20; p++) sh[1 - cur][j][p] = v[p];
        __syncthreads();
        cur = 1 - cur;
    }

    // exclusive prefix = signature of path up to time t0
    if (j == 0) {
        #pragma unroll
        for (int p = 0; p < 4; p++)  L1[p] = 0.f;
        #pragma unroll
        for (int p = 0; p < 16; p++) L2[p] = 0.f;
    } else {
        #pragma unroll
        for (int p = 0; p < 4; p++)  L1[p] = sh[cur][j - 1][p];
        #pragma unroll
        for (int p = 0; p < 16; p++) L2[p] = sh[cur][j - 1][4 + p];
    }

    // ---- pass 2: per-timestep signature, forget gate, input projection ----
    float4* Gp = g_G + ((size_t)b * TT) * UU;
    float p0 = ip[0], p1 = ip[1], p2 = ip[2];
    float x0 = p0, x1 = p1, x2 = p2;

    #pragma unroll
    for (int s = 0; s < CHUNK; s++) {
        const int t = t0 + s;
        if (s > 0) {
            float c0 = ip[s * DD + 0], c1 = ip[s * DD + 1], c2 = ip[s * DD + 2];
            float dx[4] = {dt, c0 - p0, c1 - p1, c2 - p2};
            #pragma unroll
            for (int p = 0; p < 4; p++) {
                float a = L1[p] + 0.5f * dx[p];
                #pragma unroll
                for (int q = 0; q < 4; q++)
                    L2[p * 4 + q] += a * dx[q];
            }
            #pragma unroll
            for (int p = 0; p < 4; p++) L1[p] += dx[p];
            p0 = c0; p1 = c1; p2 = c2;
            x0 = c0; x1 = c1; x2 = c2;
        }
        float scale = (t == 0) ? 1.0f : (float)(TT - 1) / (float)t;

        #pragma unroll
        for (int u = 0; u < UU; u++) {
            float acc = swf[u];  // constant term (m=0)
            #pragma unroll
            for (int p = 0; p < 4; p++)  acc += L1[p] * swf[(1 + p) * UU + u];
            #pragma unroll
            for (int p = 0; p < 16; p++) acc += L2[p] * swf[(5 + p) * UU + u];
            float f = fsig(scale * acc + sb[UU + u]);

            float zi = x0 * swi[u]          + x1 * swi[24 + u]          + x2 * swi[48 + u]          + sb[u];
            float zc = x0 * swi[8 + u]      + x1 * swi[24 + 8 + u]      + x2 * swi[48 + 8 + u]      + sb[2 * UU + u];
            float zo = x0 * swi[16 + u]     + x1 * swi[24 + 16 + u]     + x2 * swi[48 + 16 + u]     + sb[3 * UU + u];

            // 0.5 folded for sigmoid-via-tanh in kernel B; z_c stays raw
            Gp[(size_t)t * UU + u] = make_float4(0.5f * zi, zc, 0.5f * zo, f);
        }
    }
}

// ---------------------------------------------------------------------------
// Kernel B: sequential LSTM recurrence, TWO batches per lane interleaved.
// Warp = 4 groups x 8 lanes; lane u carries unit u of batches A and B.
// The two independent chains interleave in the instruction stream, so batch
// B's FMAs/MUFUs fill batch A's latency bubbles (and vice versa). One
// syncwarp + double-buffered smem slot per step-pair for the h exchange.
// ---------------------------------------------------------------------------
__global__ __launch_bounds__(32) void lstm_kernel(
    const float* __restrict__ Wr,  // (8,24)
    float* __restrict__ out)       // (B,T,8)
{
    __shared__ float hx[2][4][2][8];   // [parity][group][batch-slot][unit]

    const int lane = threadIdx.x;
    const int g = lane >> 3;
    const int u = lane & 7;
    const int bA = blockIdx.x * 8 + g * 2;
    const int bB = bA + 1;

    float wi[8], wc[8], wo[8];
    #pragma unroll
    for (int k = 0; k < 8; k++) {
        wi[k] = 0.5f * Wr[k * 24 + u];        // sigmoid path: z/2
        wc[k] =        Wr[k * 24 + 8 + u];    // tanh path: raw z
        wo[k] = 0.5f * Wr[k * 24 + 16 + u];
    }

    const float4* GA = g_G + ((size_t)bA * TT) * UU + u;
    const float4* GB = g_G + ((size_t)bB * TT) * UU + u;
    float* oA = out + ((size_t)bA * TT) * UU + u;
    float* oB = out + ((size_t)bB * TT) * UU + u;

    float hkA[8], hkB[8];
    #pragma unroll
    for (int k = 0; k < 8; k++) { hkA[k] = 0.0f; hkB[k] = 0.0f; }
    float cA = 0.0f, cB = 0.0f;

    float4 bufA[PF], bufB[PF];
    #pragma unroll
    for (int p = 0; p < PF; p++) { bufA[p] = GA[(size_t)p * UU]; bufB[p] = GB[(size_t)p * UU]; }

// one gate-dot over an hk[] vector (balanced tree)
#define DOT(hk, w, bias0, dst)                                                \
    {                                                                         \
        float a  = fmaf(hk[1], w[1], fmaf(hk[0], w[0], bias0));               \
        float bb = fmaf(hk[3], w[3], hk[2] * w[2]);                           \
        float cc = fmaf(hk[5], w[5], hk[4] * w[4]);                           \
        float dd = fmaf(hk[7], w[7], hk[6] * w[6]);                           \
        dst = (a + bb) + (cc + dd);                                           \
    }

    for (int t = 0; t < TT; t += PF) {
        #pragma unroll
        for (int k2 = 0; k2 < PF; k2++) {
            float4 vA = bufA[k2];
            float4 vB = bufB[k2];
            bufA[k2] = GA[(size_t)(t + k2 + PF) * UU];   // branchless (padded)
            bufB[k2] = GB[(size_t)(t + k2 + PF) * UU];

            float ziA, zcA, zoA, ziB, zcB, zoB;
            DOT(hkA, wi, vA.x, ziA); DOT(hkB, wi, vB.x, ziB);
            DOT(hkA, wc, vA.y, zcA); DOT(hkB, wc, vB.y, zcB);
            DOT(hkA, wo, vA.z, zoA); DOT(hkB, wo, vB.z, zoB);

            float igA = fmaf(0.5f, tanha(ziA), 0.5f);
            float igB = fmaf(0.5f, tanha(ziB), 0.5f);
            float cgA = tanha(zcA);
            float cgB = tanha(zcB);
            float ogA = fmaf(0.5f, tanha(zoA), 0.5f);
            float ogB = fmaf(0.5f, tanha(zoB), 0.5f);

            cA = fmaf(igA, cgA, vA.w * cA);
            cB = fmaf(igB, cgB, vB.w * cB);
            float hA = ogA * tanha(cA);
            float hB = ogB * tanha(cB);

            oA[(size_t)(t + k2) * UU] = hA;
            oB[(size_t)(t + k2) * UU] = hB;

            // --- h broadcast via shared memory, both batches, one sync ---
            hx[k2 & 1][g][0][u] = hA;
            hx[k2 & 1][g][1][u] = hB;
            __syncwarp();
            float4 a0 = *reinterpret_cast<const float4*>(&hx[k2 & 1][g][0][0]);
            float4 a1 = *reinterpret_cast<const float4*>(&hx[k2 & 1][g][0][4]);
            float4 b0 = *reinterpret_cast<const float4*>(&hx[k2 & 1][g][1][0]);
            float4 b1 = *reinterpret_cast<const float4*>(&hx[k2 & 1][g][1][4]);
            hkA[0] = a0.x; hkA[1] = a0.y; hkA[2] = a0.z; hkA[3] = a0.w;
            hkA[4] = a1.x; hkA[5] = a1.y; hkA[6] = a1.z; hkA[7] = a1.w;
            hkB[0] = b0.x; hkB[1] = b0.y; hkB[2] = b0.z; hkB[3] = b0.w;
            hkB[4] = b1.x; hkB[5] = b1.y; hkB[6] = b1.z; hkB[7] = b1.w;
        }
    }
#undef DOT
}

// ---------------------------------------------------------------------------
extern "C" void kernel_launch(void* const* d_in, const int* in_sizes, int n_in,
                              void* d_out, int out_size) {
    const float* inputs = (const float*)d_in[0];  // (256,4096,3)
    const float* Wi     = (const float*)d_in[1];  // (3,24)
    const float* Wr     = (const float*)d_in[2];  // (8,24)
    const float* Wf     = (const float*)d_in[3];  // (21,8)
    const float* bias   = (const float*)d_in[4];  // (32)
    float* out = (float*)d_out;                   // (256,4096,8) f32

    sig_kernel<<<BB, 256>>>(inputs, Wi, Wf, bias);
    lstm_kernel<<<BB / 8, 32>>>(Wr, out);
}

// round 12
// speedup vs baseline: 1.2135x; 1.2135x over previous
#include <cuda_runtime.h>

#define BB 256
#define TT 4096
#define DD 3
#define UU 8
#define SIGD 21
#define CHUNK 16   // TT / 256 threads (kernel A)
#define PF 4       // lstm prefetch depth (steps)

// Scratch: per (b,t,u): {0.5*z_i, z_c, 0.5*z_o, f}  (biases folded)
// Padded so the branchless prefetch ring can read past the end.
__device__ float4 g_G[(size_t)BB * TT * UU + 16 * UU];

__device__ __forceinline__ float ex2f(float x) {
    float y; asm("ex2.approx.f32 %0, %1;" : "=f"(y) : "f"(x)); return y;
}
__device__ __forceinline__ float rcpf(float x) {
    float y; asm("rcp.approx.f32 %0, %1;" : "=f"(y) : "f"(x)); return y;
}
__device__ __forceinline__ float tanha(float x) {        // MUFU.TANH, 1 op
    float y; asm("tanh.approx.f32 %0, %1;" : "=f"(y) : "f"(x)); return y;
}
__device__ __forceinline__ float fsig(float x) {         // accurate sigmoid (kernel A)
    return rcpf(1.0f + ex2f(-1.4426950408889634f * x));
}

// ---------------------------------------------------------------------------
// Kernel A: signature scan + forget gate + input projection (parallel B x T)
// ---------------------------------------------------------------------------
__global__ __launch_bounds__(256) void sig_kernel(
    const float* __restrict__ inp,   // (B,T,3)
    const float* __restrict__ Wi,    // (3,24)
    const float* __restrict__ Wf,    // (21,8)
    const float* __restrict__ bias)  // (32) = [b_i, b_f, b_c, b_o]
{
    __shared__ float sh[2][256][20];
    __shared__ float swf[SIGD * UU];   // 168
    __shared__ float swi[DD * 3 * UU]; // 72
    __shared__ float sb[4 * UU];       // 32

    const int b = blockIdx.x;
    const int j = threadIdx.x;
    if (j < SIGD * UU)   swf[j] = Wf[j];
    if (j < DD * 3 * UU) swi[j] = Wi[j];
    if (j < 4 * UU)      sb[j]  = bias[j];

    const float dt = 1.0f / (float)(TT - 1);
    const int t0 = j * CHUNK;
    const float* ip = inp + ((size_t)b * TT + t0) * DD;

    // ---- pass 1: local chunk signature (diffs t0+1 .. t0+16) ----
    float L1[4] = {0.f, 0.f, 0.f, 0.f};
    float L2[16] = {0.f};
    {
        float p0 = ip[0], p1 = ip[1], p2 = ip[2];
        #pragma unroll
        for (int s = 1; s <= CHUNK; s++) {
            int tg = t0 + s;
            if (tg <= TT - 1) {
                float c0 = ip[s * DD + 0], c1 = ip[s * DD + 1], c2 = ip[s * DD + 2];
                float dx[4] = {dt, c0 - p0, c1 - p1, c2 - p2};
                #pragma unroll
                for (int p = 0; p < 4; p++) {
                    float a = L1[p] + 0.5f * dx[p];
                    #pragma unroll
                    for (int q = 0; q < 4; q++)
                        L2[p * 4 + q] += a * dx[q];
                }
                #pragma unroll
                for (int p = 0; p < 4; p++) L1[p] += dx[p];
                p0 = c0; p1 = c1; p2 = c2;
            }
        }
    }

    // ---- inclusive Hillis-Steele scan of Chen states over 256 chunks ----
    #pragma unroll
    for (int p = 0; p < 4; p++)  sh[0][j][p] = L1[p];
    #pragma unroll
    for (int p = 0; p < 16; p++) sh[0][j][4 + p] = L2[p];
    __syncthreads();

    int cur = 0;
    for (int ofs = 1; ofs < 256; ofs <<= 1) {
        float v[20];
        #pragma unroll
        for (int p = 0; p < 20; p++) v[p] = sh[cur][j][p];
        if (j >= ofs) {
            const float* a = sh[cur][j - ofs];  // earlier aggregate
            float o[20];
            #pragma unroll
            for (int p = 0; p < 4; p++) o[p] = a[p] + v[p];
            #pragma unroll
            for (int p = 0; p < 4; p++)
                #pragma unroll
                for (int q = 0; q < 4; q++)
                    o[4 + p * 4 + q] = a[4 + p * 4 + q] + v[4 + p * 4 + q] + a[p] * v[q];
            #pragma unroll
            for (int p = 0; p < 20; p++) v[p] = o[p];
        }
        #pragma unroll
        for (int p = 0; p < 20; p++) sh[1 - cur][j][p] = v[p];
        __syncthreads();
        cur = 1 - cur;
    }

    // exclusive prefix = signature of path up to time t0
    if (j == 0) {
        #pragma unroll
        for (int p = 0; p < 4; p++)  L1[p] = 0.f;
        #pragma unroll
        for (int p = 0; p < 16; p++) L2[p] = 0.f;
    } else {
        #pragma unroll
        for (int p = 0; p < 4; p++)  L1[p] = sh[cur][j - 1][p];
        #pragma unroll
        for (int p = 0; p < 16; p++) L2[p] = sh[cur][j - 1][4 + p];
    }

    // ---- pass 2: per-timestep signature, forget gate, input projection ----
    float4* Gp = g_G + ((size_t)b * TT) * UU;
    float p0 = ip[0], p1 = ip[1], p2 = ip[2];
    float x0 = p0, x1 = p1, x2 = p2;

    #pragma unroll
    for (int s = 0; s < CHUNK; s++) {
        const int t = t0 + s;
        if (s > 0) {
            float c0 = ip[s * DD + 0], c1 = ip[s * DD + 1], c2 = ip[s * DD + 2];
            float dx[4] = {dt, c0 - p0, c1 - p1, c2 - p2};
            #pragma unroll
            for (int p = 0; p < 4; p++) {
                float a = L1[p] + 0.5f * dx[p];
                #pragma unroll
                for (int q = 0; q < 4; q++)
                    L2[p * 4 + q] += a * dx[q];
            }
            #pragma unroll
            for (int p = 0; p < 4; p++) L1[p] += dx[p];
            p0 = c0; p1 = c1; p2 = c2;
            x0 = c0; x1 = c1; x2 = c2;
        }
        // 4095/t via rcp.approx (rel err ~2^-22, harmless before sigmoid)
        float scale = (t == 0) ? 1.0f : 4095.0f * rcpf((float)t);

        #pragma unroll
        for (int u = 0; u < UU; u++) {
            float acc = swf[u];  // constant term (m=0)
            #pragma unroll
            for (int p = 0; p < 4; p++)  acc += L1[p] * swf[(1 + p) * UU + u];
            #pragma unroll
            for (int p = 0; p < 16; p++) acc += L2[p] * swf[(5 + p) * UU + u];
            float f = fsig(scale * acc + sb[UU + u]);

            float zi = x0 * swi[u]          + x1 * swi[24 + u]          + x2 * swi[48 + u]          + sb[u];
            float zc = x0 * swi[8 + u]      + x1 * swi[24 + 8 + u]      + x2 * swi[48 + 8 + u]      + sb[2 * UU + u];
            float zo = x0 * swi[16 + u]     + x1 * swi[24 + 16 + u]     + x2 * swi[48 + 16 + u]     + sb[3 * UU + u];

            // 0.5 folded for sigmoid-via-tanh in kernel B; z_c stays raw
            Gp[(size_t)t * UU + u] = make_float4(0.5f * zi, zc, 0.5f * zo, f);
        }
    }
}

// ---------------------------------------------------------------------------
// Kernel B: sequential LSTM recurrence. Warp = 4 batches x 8 lanes (lane=unit)
// Warp-synchronous smem h-exchange: control flow is fully convergent, so the
// warp is lockstep; STS -> LDS ordering within one warp is guaranteed by the
// LSU, and asm volatile keeps the compiler from reordering. No __syncwarp.
// Pointer-bump addressing gives compile-time LDG/STG offsets. PF=4 keeps the
// unrolled body inside the 6KB L0 I-cache.
// ---------------------------------------------------------------------------
__global__ __launch_bounds__(32) void lstm_kernel(
    const float* __restrict__ Wr,  // (8,24)
    float* __restrict__ out)       // (B,T,8)
{
    __shared__ float hx[2][4][8];   // [parity][group][unit]

    const int lane = threadIdx.x & 31;
    const int g = lane >> 3;
    const int u = lane & 7;
    const int b = blockIdx.x * 4 + g;

    float wi[8], wc[8], wo[8];
    #pragma unroll
    for (int k = 0; k < 8; k++) {
        wi[k] = 0.5f * Wr[k * 24 + u];        // sigmoid path: z/2
        wc[k] =        Wr[k * 24 + 8 + u];    // tanh path: raw z
        wo[k] = 0.5f * Wr[k * 24 + 16 + u];
    }

    // shared-memory addresses (32-bit) for the exchange, both parities
    const unsigned sbase = (unsigned)__cvta_generic_to_shared(&hx[0][0][0]);
    const unsigned sts0 = sbase + (g * 8 + u) * 4;
    const unsigned sts1 = sts0 + 128;
    const unsigned lds0 = sbase + g * 32;
    const unsigned lds1 = lds0 + 128;

    const float4* Gp = g_G + ((size_t)b * TT) * UU + u;
    float*        op = out + ((size_t)b * TT) * UU + u;

    float hk[8];
    #pragma unroll
    for (int k = 0; k < 8; k++) hk[k] = 0.0f;   // h_{-1} = 0
    float c = 0.0f;

    float4 buf[PF];
    #pragma unroll
    for (int p = 0; p < PF; p++) buf[p] = __ldcs(&Gp[p * UU]);

    for (int t = 0; t < TT; t += PF) {
        #pragma unroll
        for (int k2 = 0; k2 < PF; k2++) {
            float4 v = buf[k2];
            buf[k2] = __ldcs(&Gp[(k2 + PF) * UU]);   // compile-time offset
            float fc = v.w * c;                      // off-chain early

            // balanced tree dots
            float zi, zc, zo;
            {
                float a  = fmaf(hk[1], wi[1], fmaf(hk[0], wi[0], v.x));
                float bb = fmaf(hk[3], wi[3], hk[2] * wi[2]);
                float cc = fmaf(hk[5], wi[5], hk[4] * wi[4]);
                float dd = fmaf(hk[7], wi[7], hk[6] * wi[6]);
                zi = (a + bb) + (cc + dd);
            }
            {
                float a  = fmaf(hk[1], wc[1], fmaf(hk[0], wc[0], v.y));
                float bb = fmaf(hk[3], wc[3], hk[2] * wc[2]);
                float cc = fmaf(hk[5], wc[5], hk[4] * wc[4]);
                float dd = fmaf(hk[7], wc[7], hk[6] * wc[6]);
                zc = (a + bb) + (cc + dd);
            }
            {
                float a  = fmaf(hk[1], wo[1], fmaf(hk[0], wo[0], v.z));
                float bb = fmaf(hk[3], wo[3], hk[2] * wo[2]);
                float cc = fmaf(hk[5], wo[5], hk[4] * wo[4]);
                float dd = fmaf(hk[7], wo[7], hk[6] * wo[6]);
                zo = (a + bb) + (cc + dd);
            }

            float ig = fmaf(0.5f, tanha(zi), 0.5f);   // sigmoid(z_i)
            float cg = tanha(zc);                     // tanh(z_c)
            float og = fmaf(0.5f, tanha(zo), 0.5f);   // sigmoid(z_o)

            c = fmaf(ig, cg, fc);                     // f*c + i*chat
            float h = og * tanha(c);                  // o * tanh(c)

            // --- warp-synchronous h exchange (no barrier) ---
            const unsigned sa = (k2 & 1) ? sts1 : sts0;
            const unsigned la = (k2 & 1) ? lds1 : lds0;
            asm volatile("st.shared.f32 [%0], %1;" :: "r"(sa), "f"(h));
            asm volatile("ld.shared.v4.f32 {%0,%1,%2,%3}, [%4];"
                         : "=f"(hk[0]), "=f"(hk[1]), "=f"(hk[2]), "=f"(hk[3])
                         : "r"(la));
            asm volatile("ld.shared.v4.f32 {%0,%1,%2,%3}, [%4];"
                         : "=f"(hk[4]), "=f"(hk[5]), "=f"(hk[6]), "=f"(hk[7])
                         : "r"(la + 16));

            __stcs(&op[k2 * UU], h);                  // streaming store, off-chain
        }
        Gp += PF * UU;
        op += PF * UU;
    }
}

// ---------------------------------------------------------------------------
extern "C" void kernel_launch(void* const* d_in, const int* in_sizes, int n_in,
                              void* d_out, int out_size) {
    const float* inputs = (const float*)d_in[0];  // (256,4096,3)
    const float* Wi     = (const float*)d_in[1];  // (3,24)
    const float* Wr     = (const float*)d_in[2];  // (8,24)
    const float* Wf     = (const float*)d_in[3];  // (21,8)
    const float* bias   = (const float*)d_in[4];  // (32)
    float* out = (float*)d_out;                   // (256,4096,8) f32

    sig_kernel<<<BB, 256>>>(inputs, Wi, Wf, bias);
    lstm_kernel<<<BB / 4, 32>>>(Wr, out);
}